// round 2
// baseline (speedup 1.0000x reference)
#include <cuda_runtime.h>
#include <cuda_fp16.h>
#include <cstdint>

// ============================================================================
// PiLinear: out = qz(qz(x) @ qz(W)^T + b), qz(v) = round(v/u)*u, u = (pi/2)/256
//
// Exact-integer path: i = round(x/u) (|i| < ~1000, exact in f16),
// j = round(w/u) (|j| < ~25, exact in f16). f16 mma.sync with f32 accumulation
// computes S = sum(i*j) exactly (|S| << 2^24). Epilogue reconstructs
// round(S*u)*u (+bias, requantize) == reference up to its own f32 rounding.
//
// NOTE: compile target is plain sm_103 (no 'a') -> tcgen05/TMEM unavailable.
// This uses the legacy HMMA path: cp.async multi-stage + ldmatrix + mma.sync.
// ============================================================================

#define U_F 0.006135923151542565f   // (pi/2)/256 rounded to f32

static constexpr int M_DIM = 8192;
static constexpr int N_DIM = 4096;
static constexpr int K_DIM = 4096;

static constexpr int BM = 128, BN = 128, BK = 64;
static constexpr int STAGES = 4;
static constexpr int KT = K_DIM / BK;                         // 64 k-tiles
static constexpr int A_STAGE_BYTES = BM * BK * 2;             // 16384
static constexpr int B_STAGE_BYTES = BN * BK * 2;             // 16384
static constexpr int STAGE_BYTES = A_STAGE_BYTES + B_STAGE_BYTES;  // 32768
static constexpr int SMEM_SIZE = STAGES * STAGE_BYTES;        // 131072

static constexpr int MTILES = M_DIM / BM;   // 64
static constexpr int NTILES = N_DIM / BN;   // 32

// Quantized f16-integer operand copies (scratch; no allocation allowed).
static __device__ __align__(128) __half g_A16[(size_t)M_DIM * K_DIM];
static __device__ __align__(128) __half g_B16[(size_t)N_DIM * K_DIM];

// ----------------------------------------------------------------------------
// PTX helpers (sm_103-base-safe: cp.async / ldmatrix / mma.sync only)
// ----------------------------------------------------------------------------
__device__ __forceinline__ uint32_t smem_u32(const void* p) {
    uint32_t a;
    asm("{ .reg .u64 t; cvta.to.shared.u64 t, %1; cvt.u32.u64 %0, t; }"
        : "=r"(a) : "l"(p));
    return a;
}

#define CP_ASYNC16(dst, src) \
    asm volatile("cp.async.cg.shared.global [%0], [%1], 16;" \
                 :: "r"(dst), "l"(src) : "memory")
#define CP_COMMIT() asm volatile("cp.async.commit_group;" ::: "memory")
#define CP_WAIT2()  asm volatile("cp.async.wait_group 2;"  ::: "memory")

#define LDSM4(r, addr) \
    asm volatile("ldmatrix.sync.aligned.m8n8.x4.shared.b16 {%0,%1,%2,%3}, [%4];" \
                 : "=r"((r)[0]), "=r"((r)[1]), "=r"((r)[2]), "=r"((r)[3]) \
                 : "r"(addr))

#define MMA16816(d, a, b0, b1) \
    asm volatile("mma.sync.aligned.m16n8k16.row.col.f32.f16.f16.f32 " \
                 "{%0,%1,%2,%3}, {%4,%5,%6,%7}, {%8,%9}, {%0,%1,%2,%3};" \
                 : "+f"((d)[0]), "+f"((d)[1]), "+f"((d)[2]), "+f"((d)[3]) \
                 : "r"((a)[0]), "r"((a)[1]), "r"((a)[2]), "r"((a)[3]), \
                   "r"(b0), "r"(b1))

// ----------------------------------------------------------------------------
// Quantize-to-f16 pack kernel: d[i] = (half)round(s[i]/u)  (exact integer)
// 8 elements per thread, fully coalesced 16B stores.
// ----------------------------------------------------------------------------
__global__ void __launch_bounds__(256) quant_kernel(const float* __restrict__ s,
                                                    __half* __restrict__ d) {
    const size_t i = ((size_t)blockIdx.x * 256 + threadIdx.x) * 8;
    const float4 v0 = *reinterpret_cast<const float4*>(s + i);
    const float4 v1 = *reinterpret_cast<const float4*>(s + i + 4);
    unsigned short h[8];
    h[0] = __half_as_ushort(__float2half_rn(rintf(__fdiv_rn(v0.x, U_F))));
    h[1] = __half_as_ushort(__float2half_rn(rintf(__fdiv_rn(v0.y, U_F))));
    h[2] = __half_as_ushort(__float2half_rn(rintf(__fdiv_rn(v0.z, U_F))));
    h[3] = __half_as_ushort(__float2half_rn(rintf(__fdiv_rn(v0.w, U_F))));
    h[4] = __half_as_ushort(__float2half_rn(rintf(__fdiv_rn(v1.x, U_F))));
    h[5] = __half_as_ushort(__float2half_rn(rintf(__fdiv_rn(v1.y, U_F))));
    h[6] = __half_as_ushort(__float2half_rn(rintf(__fdiv_rn(v1.z, U_F))));
    h[7] = __half_as_ushort(__float2half_rn(rintf(__fdiv_rn(v1.w, U_F))));
    uint4 p;
    p.x = (uint32_t)h[0] | ((uint32_t)h[1] << 16);
    p.y = (uint32_t)h[2] | ((uint32_t)h[3] << 16);
    p.z = (uint32_t)h[4] | ((uint32_t)h[5] << 16);
    p.w = (uint32_t)h[6] | ((uint32_t)h[7] << 16);
    *reinterpret_cast<uint4*>(d + i) = p;
}

// ----------------------------------------------------------------------------
// GEMM: 128x128x64 CTA tile, 4-stage cp.async pipeline, 8 warps (4x2),
// warp tile 32x64 via mma.sync m16n8k16, fused pi-quantize epilogue.
// ----------------------------------------------------------------------------
__device__ __forceinline__ void load_stage(uint32_t sbase, int mbase, int nbase,
                                           int kbase, int tid) {
    // A: 128 rows x 64 halves (128B/row) = 1024 16B chunks; same for B.
#pragma unroll
    for (int i = 0; i < 4; i++) {
        const int c = tid + i * 256;
        const int row = c >> 3, col16 = c & 7;
        const uint32_t dst = sbase + row * 128 + ((col16 ^ (row & 7)) << 4);
        const void* src = g_A16 + (size_t)(mbase + row) * K_DIM + kbase + col16 * 8;
        CP_ASYNC16(dst, src);
    }
#pragma unroll
    for (int i = 0; i < 4; i++) {
        const int c = tid + i * 256;
        const int row = c >> 3, col16 = c & 7;
        const uint32_t dst = sbase + A_STAGE_BYTES + row * 128 + ((col16 ^ (row & 7)) << 4);
        const void* src = g_B16 + (size_t)(nbase + row) * K_DIM + kbase + col16 * 8;
        CP_ASYNC16(dst, src);
    }
}

__global__ void __launch_bounds__(256, 1)
gemm_kernel(const float* __restrict__ bias, float* __restrict__ out) {
    extern __shared__ __align__(1024) char smem[];
    const uint32_t sbase = smem_u32(smem);
    const int tid = threadIdx.x;
    const int lane = tid & 31;
    const int w = tid >> 5;

    // banded rasterization: 8 m-tiles x 32 n-tiles per band (256 CTAs/band)
    const int bid = blockIdx.x;
    const int band = bid >> 8;
    const int rem = bid & 255;
    const int mt = band * 8 + (rem & 7);
    const int nt = rem >> 3;
    const int mbase = mt * BM, nbase = nt * BN;

    // prologue: fill STAGES-1 stages
#pragma unroll
    for (int s = 0; s < STAGES - 1; s++) {
        load_stage(sbase + s * STAGE_BYTES, mbase, nbase, s * BK, tid);
        CP_COMMIT();
    }

    const int mwarp = w >> 1;        // 0..3 -> 32-row slices
    const int nwarp = w & 1;         // 0..1 -> 64-col slices
    const int x7 = lane & 7;

    // per-lane invariant smem byte offsets (relative to stage base)
    uint32_t aoff[2], boff[4];
#pragma unroll
    for (int mi = 0; mi < 2; mi++)
        aoff[mi] = (uint32_t)((mwarp * 32 + mi * 16 + (lane & 15)) << 7);
#pragma unroll
    for (int nb = 0; nb < 4; nb++)
        boff[nb] = (uint32_t)(A_STAGE_BYTES +
                   ((nwarp * 64 + nb * 16 + (lane & 7) + ((lane >> 4) << 3)) << 7));
    const int acol = lane >> 4;          // A: +8 in k for lanes 16-31
    const int bcol = (lane >> 3) & 1;    // B: +8 in k pattern

    float acc[2][8][4];
#pragma unroll
    for (int mi = 0; mi < 2; mi++)
#pragma unroll
        for (int nj = 0; nj < 8; nj++)
#pragma unroll
            for (int e = 0; e < 4; e++) acc[mi][nj][e] = 0.f;

    for (int kt = 0; kt < KT; kt++) {
        CP_WAIT2();
        __syncthreads();
        const uint32_t st = sbase + (kt & (STAGES - 1)) * STAGE_BYTES;
#pragma unroll
        for (int ks = 0; ks < 4; ks++) {
            uint32_t a[2][4], b[4][4];
#pragma unroll
            for (int mi = 0; mi < 2; mi++)
                LDSM4(a[mi], st + aoff[mi] + ((uint32_t)((ks * 2 + acol) ^ x7) << 4));
#pragma unroll
            for (int nb = 0; nb < 4; nb++)
                LDSM4(b[nb], st + boff[nb] + ((uint32_t)((ks * 2 + bcol) ^ x7) << 4));
#pragma unroll
            for (int mi = 0; mi < 2; mi++)
#pragma unroll
                for (int nj = 0; nj < 8; nj++)
                    MMA16816(acc[mi][nj], a[mi],
                             b[nj >> 1][(nj & 1) * 2], b[nj >> 1][(nj & 1) * 2 + 1]);
        }
        const int next = kt + STAGES - 1;
        if (next < KT)
            load_stage(sbase + (next & (STAGES - 1)) * STAGE_BYTES,
                       mbase, nbase, next * BK, tid);
        CP_COMMIT();
    }

    // ---- epilogue: exact S -> qz(S*u) (+bias) -> qz -> GMEM ----
    const int row0 = mbase + mwarp * 32;
    const int col0 = nbase + nwarp * 64;
    const int tr = lane >> 2;
    const int tc = (lane & 3) * 2;
#pragma unroll
    for (int mi = 0; mi < 2; mi++) {
#pragma unroll
        for (int rr = 0; rr < 2; rr++) {
            const int row = row0 + mi * 16 + rr * 8 + tr;
            float* orow = out + (size_t)row * N_DIM + col0;
#pragma unroll
            for (int nj = 0; nj < 8; nj++) {
                const int c = nj * 8 + tc;
                float2 o;
#pragma unroll
                for (int e = 0; e < 2; e++) {
                    const float sv = acc[mi][nj][rr * 2 + e];        // exact int S
                    const float q  = rintf(__fmul_rn(sv, U_F));      // round(S*u)
                    const float cv = __fmul_rn(q, U_F);              // qz(dot)
                    const float tv = cv + bias[col0 + c + e];        // + bias
                    (&o.x)[e] = __fmul_rn(rintf(__fdiv_rn(tv, U_F)), U_F); // qz
                }
                *reinterpret_cast<float2*>(orow + c) = o;
            }
        }
    }
}

// ----------------------------------------------------------------------------
// Host launcher (graph-capturable: kernel launches only)
// ----------------------------------------------------------------------------
extern "C" void kernel_launch(void* const* d_in, const int* in_sizes, int n_in,
                              void* d_out, int out_size) {
    const float* x = (const float*)d_in[0];   // [8192, 4096]
    const float* wgt = (const float*)d_in[1]; // [4096, 4096]
    const float* b = (const float*)d_in[2];   // [4096]
    float* out = (float*)d_out;               // [8192, 4096]

    void* a16 = nullptr; void* b16 = nullptr;
    cudaGetSymbolAddress(&a16, g_A16);
    cudaGetSymbolAddress(&b16, g_B16);

    // quantize operands to f16 integers
    quant_kernel<<<(int)(((size_t)M_DIM * K_DIM / 8) / 256), 256>>>(x, (__half*)a16);
    quant_kernel<<<(int)(((size_t)N_DIM * K_DIM / 8) / 256), 256>>>(wgt, (__half*)b16);

    // GEMM + fused epilogue
    static bool attr_set = false;
    if (!attr_set) {
        cudaFuncSetAttribute(gemm_kernel,
                             cudaFuncAttributeMaxDynamicSharedMemorySize, SMEM_SIZE);
        attr_set = true;
    }
    gemm_kernel<<<MTILES * NTILES, 256, SMEM_SIZE>>>(b, out);
}

// round 4
// speedup vs baseline: 1.0724x; 1.0724x over previous
#include <cuda_runtime.h>
#include <cuda_fp16.h>
#include <cstdint>

// ============================================================================
// PiLinear: out = qz(qz(x) @ qz(W)^T + b), qz(v) = round(v/u)*u, u = (pi/2)/256
//
// Exact-integer path: i = round(x/u) (|i| < ~1000, exact in f16),
// j = round(w/u) (|j| < ~25, exact in f16). f16 mma.sync with f32 accumulation
// computes S = sum(i*j) exactly (|S| << 2^24). Epilogue reconstructs
// round(S*u)*u (+bias, requantize) == reference up to its own f32 rounding.
//
// Plain sm_103 target (no tcgen05): cp.async + ldmatrix + mma.sync HMMA path.
// R4 = R3 with the stage-index wraparound bug fixed (rolling cursors instead
// of a broken one-shot subtraction that indexed stage 3 of 3).
// ============================================================================

#define U_F 0.006135923151542565f   // (pi/2)/256 rounded to f32

static constexpr int M_DIM = 8192;
static constexpr int N_DIM = 4096;
static constexpr int K_DIM = 4096;

static constexpr int BM = 128, BN = 256, BK = 64;
static constexpr int STAGES = 3;
static constexpr int KT = K_DIM / BK;                         // 64 k-tiles
static constexpr int A_STAGE_BYTES = BM * BK * 2;             // 16384
static constexpr int B_STAGE_BYTES = BN * BK * 2;             // 32768
static constexpr int STAGE_BYTES = A_STAGE_BYTES + B_STAGE_BYTES;  // 49152
static constexpr int SMEM_SIZE = STAGES * STAGE_BYTES;        // 147456

static constexpr int MTILES = M_DIM / BM;   // 64
static constexpr int NTILES = N_DIM / BN;   // 16

// Quantized f16-integer operand copies (scratch; no allocation allowed).
static __device__ __align__(128) __half g_A16[(size_t)M_DIM * K_DIM];
static __device__ __align__(128) __half g_B16[(size_t)N_DIM * K_DIM];

// ----------------------------------------------------------------------------
// PTX helpers
// ----------------------------------------------------------------------------
__device__ __forceinline__ uint32_t smem_u32(const void* p) {
    uint32_t a;
    asm("{ .reg .u64 t; cvta.to.shared.u64 t, %1; cvt.u32.u64 %0, t; }"
        : "=r"(a) : "l"(p));
    return a;
}

#define CP_ASYNC16(dst, src) \
    asm volatile("cp.async.cg.shared.global [%0], [%1], 16;" \
                 :: "r"(dst), "l"(src) : "memory")
#define CP_COMMIT() asm volatile("cp.async.commit_group;" ::: "memory")
#define CP_WAIT1()  asm volatile("cp.async.wait_group 1;"  ::: "memory")

#define LDSM4(r, addr) \
    asm volatile("ldmatrix.sync.aligned.m8n8.x4.shared.b16 {%0,%1,%2,%3}, [%4];" \
                 : "=r"((r)[0]), "=r"((r)[1]), "=r"((r)[2]), "=r"((r)[3]) \
                 : "r"(addr))

#define MMA16816(d, a, b0, b1) \
    asm volatile("mma.sync.aligned.m16n8k16.row.col.f32.f16.f16.f32 " \
                 "{%0,%1,%2,%3}, {%4,%5,%6,%7}, {%8,%9}, {%0,%1,%2,%3};" \
                 : "+f"((d)[0]), "+f"((d)[1]), "+f"((d)[2]), "+f"((d)[3]) \
                 : "r"((a)[0]), "r"((a)[1]), "r"((a)[2]), "r"((a)[3]), \
                   "r"(b0), "r"(b1))

// ----------------------------------------------------------------------------
// Quantize-to-f16 pack kernel (DRAM-roofline-bound already; unchanged)
// ----------------------------------------------------------------------------
__global__ void __launch_bounds__(256) quant_kernel(const float* __restrict__ s,
                                                    __half* __restrict__ d) {
    const size_t i = ((size_t)blockIdx.x * 256 + threadIdx.x) * 8;
    const float4 v0 = *reinterpret_cast<const float4*>(s + i);
    const float4 v1 = *reinterpret_cast<const float4*>(s + i + 4);
    unsigned short h[8];
    h[0] = __half_as_ushort(__float2half_rn(rintf(__fdiv_rn(v0.x, U_F))));
    h[1] = __half_as_ushort(__float2half_rn(rintf(__fdiv_rn(v0.y, U_F))));
    h[2] = __half_as_ushort(__float2half_rn(rintf(__fdiv_rn(v0.z, U_F))));
    h[3] = __half_as_ushort(__float2half_rn(rintf(__fdiv_rn(v0.w, U_F))));
    h[4] = __half_as_ushort(__float2half_rn(rintf(__fdiv_rn(v1.x, U_F))));
    h[5] = __half_as_ushort(__float2half_rn(rintf(__fdiv_rn(v1.y, U_F))));
    h[6] = __half_as_ushort(__float2half_rn(rintf(__fdiv_rn(v1.z, U_F))));
    h[7] = __half_as_ushort(__float2half_rn(rintf(__fdiv_rn(v1.w, U_F))));
    uint4 p;
    p.x = (uint32_t)h[0] | ((uint32_t)h[1] << 16);
    p.y = (uint32_t)h[2] | ((uint32_t)h[3] << 16);
    p.z = (uint32_t)h[4] | ((uint32_t)h[5] << 16);
    p.w = (uint32_t)h[6] | ((uint32_t)h[7] << 16);
    *reinterpret_cast<uint4*>(d + i) = p;
}

// ----------------------------------------------------------------------------
// Stage loader: A 16KB (1024 x 16B), B 32KB (2048 x 16B), XOR-swizzled rows.
// ----------------------------------------------------------------------------
__device__ __forceinline__ void load_stage(uint32_t sbase, int mbase, int nbase,
                                           int kbase, int tid) {
#pragma unroll
    for (int i = 0; i < 4; i++) {
        const int c = tid + i * 256;
        const int row = c >> 3, col16 = c & 7;
        const uint32_t dst = sbase + row * 128 + ((col16 ^ (row & 7)) << 4);
        const void* src = g_A16 + (size_t)(mbase + row) * K_DIM + kbase + col16 * 8;
        CP_ASYNC16(dst, src);
    }
#pragma unroll
    for (int i = 0; i < 8; i++) {
        const int c = tid + i * 256;
        const int row = c >> 3, col16 = c & 7;
        const uint32_t dst = sbase + A_STAGE_BYTES + row * 128 + ((col16 ^ (row & 7)) << 4);
        const void* src = g_B16 + (size_t)(nbase + row) * K_DIM + kbase + col16 * 8;
        CP_ASYNC16(dst, src);
    }
}

// ----------------------------------------------------------------------------
// GEMM: 128x256x64 CTA tile, 3-stage cp.async pipeline, 8 warps (4M x 2N),
// warp tile 32x128 via mma.sync m16n8k16, fused pi-quantize epilogue.
// ----------------------------------------------------------------------------
__global__ void __launch_bounds__(256, 1)
gemm_kernel(const float* __restrict__ bias, float* __restrict__ out) {
    extern __shared__ __align__(1024) char smem[];
    const uint32_t sbase = smem_u32(smem);
    const int tid = threadIdx.x;
    const int lane = tid & 31;
    const int w = tid >> 5;

    // banded rasterization: 8 m-tiles x 16 n-tiles per band (128 CTAs/band)
    const int bid = blockIdx.x;
    const int band = bid >> 7;
    const int rem = bid & 127;
    const int mt = band * 8 + (rem & 7);
    const int nt = rem >> 3;
    const int mbase = mt * BM, nbase = nt * BN;

    // prologue: fill STAGES-1 = 2 stages (k-tiles 0 and 1)
#pragma unroll
    for (int s = 0; s < STAGES - 1; s++) {
        load_stage(sbase + s * STAGE_BYTES, mbase, nbase, s * BK, tid);
        CP_COMMIT();
    }

    const int mwarp = w >> 1;        // 0..3 -> 32-row slices
    const int nwarp = w & 1;         // 0..1 -> 128-col slices
    const int x7 = lane & 7;

    // per-lane invariant smem byte offsets (relative to stage base)
    uint32_t aoff[2], boff[8];
#pragma unroll
    for (int mi = 0; mi < 2; mi++)
        aoff[mi] = (uint32_t)((mwarp * 32 + mi * 16 + (lane & 15)) << 7);
#pragma unroll
    for (int nb = 0; nb < 8; nb++)
        boff[nb] = (uint32_t)(A_STAGE_BYTES +
                   ((nwarp * 128 + nb * 16 + (lane & 7) + ((lane >> 4) << 3)) << 7));
    const int acol = lane >> 4;          // A: +8 in k for lanes 16-31
    const int bcol = (lane >> 3) & 1;    // B: +8 in k pattern

    float acc[2][16][4];
#pragma unroll
    for (int mi = 0; mi < 2; mi++)
#pragma unroll
        for (int nj = 0; nj < 16; nj++)
#pragma unroll
            for (int e = 0; e < 4; e++) acc[mi][nj][e] = 0.f;

    // rolling stage cursors: compute stage and next-load stage
    int cmp_s = 0;              // stage holding k-tile kt
    int ld_s  = STAGES - 1;     // next free stage slot

    for (int kt = 0; kt < KT; kt++) {
        CP_WAIT1();
        __syncthreads();
        // issue next stage loads first; the syncthreads above guarantees all
        // warps finished computing the stage being overwritten (kt-1's slot).
        const int next = kt + STAGES - 1;
        if (next < KT) {
            load_stage(sbase + ld_s * STAGE_BYTES, mbase, nbase, next * BK, tid);
        }
        CP_COMMIT();
        ld_s = (ld_s + 1 == STAGES) ? 0 : ld_s + 1;

        const uint32_t st = sbase + cmp_s * STAGE_BYTES;
        cmp_s = (cmp_s + 1 == STAGES) ? 0 : cmp_s + 1;
#pragma unroll
        for (int ks = 0; ks < 4; ks++) {
            uint32_t a[2][4];
#pragma unroll
            for (int mi = 0; mi < 2; mi++)
                LDSM4(a[mi], st + aoff[mi] + ((uint32_t)((ks * 2 + acol) ^ x7) << 4));
#pragma unroll
            for (int half = 0; half < 2; half++) {
                uint32_t b[4][4];
#pragma unroll
                for (int q = 0; q < 4; q++)
                    LDSM4(b[q], st + boff[half * 4 + q] +
                                ((uint32_t)((ks * 2 + bcol) ^ x7) << 4));
#pragma unroll
                for (int mi = 0; mi < 2; mi++)
#pragma unroll
                    for (int jj = 0; jj < 8; jj++) {
                        const int nj = half * 8 + jj;
                        MMA16816(acc[mi][nj], a[mi],
                                 b[jj >> 1][(jj & 1) * 2], b[jj >> 1][(jj & 1) * 2 + 1]);
                    }
            }
        }
    }

    // ---- epilogue: exact S -> qz(S*u) (+bias) -> qz -> GMEM ----
    const int row0 = mbase + mwarp * 32;
    const int col0 = nbase + nwarp * 128;
    const int tr = lane >> 2;
    const int tc = (lane & 3) * 2;
#pragma unroll
    for (int mi = 0; mi < 2; mi++) {
#pragma unroll
        for (int rr = 0; rr < 2; rr++) {
            const int row = row0 + mi * 16 + rr * 8 + tr;
            float* orow = out + (size_t)row * N_DIM + col0;
#pragma unroll
            for (int nj = 0; nj < 16; nj++) {
                const int c = nj * 8 + tc;
                float2 o;
#pragma unroll
                for (int e = 0; e < 2; e++) {
                    const float sv = acc[mi][nj][rr * 2 + e];        // exact int S
                    const float q  = rintf(__fmul_rn(sv, U_F));      // round(S*u)
                    const float cv = __fmul_rn(q, U_F);              // qz(dot)
                    const float tv = cv + __ldg(bias + col0 + c + e);// + bias
                    (&o.x)[e] = __fmul_rn(rintf(__fdiv_rn(tv, U_F)), U_F); // qz
                }
                *reinterpret_cast<float2*>(orow + c) = o;
            }
        }
    }
}

// ----------------------------------------------------------------------------
// Host launcher (graph-capturable: kernel launches only)
// ----------------------------------------------------------------------------
extern "C" void kernel_launch(void* const* d_in, const int* in_sizes, int n_in,
                              void* d_out, int out_size) {
    const float* x = (const float*)d_in[0];   // [8192, 4096]
    const float* wgt = (const float*)d_in[1]; // [4096, 4096]
    const float* b = (const float*)d_in[2];   // [4096]
    float* out = (float*)d_out;               // [8192, 4096]

    void* a16 = nullptr; void* b16 = nullptr;
    cudaGetSymbolAddress(&a16, g_A16);
    cudaGetSymbolAddress(&b16, g_B16);

    // quantize operands to f16 integers
    quant_kernel<<<(int)(((size_t)M_DIM * K_DIM / 8) / 256), 256>>>(x, (__half*)a16);
    quant_kernel<<<(int)(((size_t)N_DIM * K_DIM / 8) / 256), 256>>>(wgt, (__half*)b16);

    // GEMM + fused epilogue
    static bool attr_set = false;
    if (!attr_set) {
        cudaFuncSetAttribute(gemm_kernel,
                             cudaFuncAttributeMaxDynamicSharedMemorySize, SMEM_SIZE);
        attr_set = true;
    }
    gemm_kernel<<<MTILES * NTILES, 256, SMEM_SIZE>>>(b, out);
}

// round 5
// speedup vs baseline: 1.1466x; 1.0691x over previous
#include <cuda_runtime.h>
#include <cuda_fp16.h>
#include <cstdint>

// ============================================================================
// PiLinear: out = qz(qz(x) @ qz(W)^T + b), qz(v) = round(v/u)*u, u = (pi/2)/256
//
// Exact-integer path: i = round(x/u), j = round(w/u) exact in f16; f16 MMA
// with f32 accumulation computes S = sum(i*j) exactly. Epilogue reconstructs
// round(S*u)*u (+bias, requantize).
//
// R5: warp tiling 4Mx2N (32x128) -> 2Mx4N (64x64). Cuts CTA smem LDSM traffic
// per k-tile from 160KB to 128KB (crossbar occupancy 79% -> 67%), LDSM issues
// per warp -20%. Epilogue div -> reciprocal mul.
// ============================================================================

#define U_F   0.006135923151542565f   // (pi/2)/256
#define INVU_F 162.97466172610083f    // 512/pi

static constexpr int M_DIM = 8192;
static constexpr int N_DIM = 4096;
static constexpr int K_DIM = 4096;

static constexpr int BM = 128, BN = 256, BK = 64;
static constexpr int STAGES = 3;
static constexpr int KT = K_DIM / BK;                         // 64 k-tiles
static constexpr int A_STAGE_BYTES = BM * BK * 2;             // 16384
static constexpr int B_STAGE_BYTES = BN * BK * 2;             // 32768
static constexpr int STAGE_BYTES = A_STAGE_BYTES + B_STAGE_BYTES;  // 49152
static constexpr int SMEM_SIZE = STAGES * STAGE_BYTES;        // 147456

static constexpr int MTILES = M_DIM / BM;   // 64
static constexpr int NTILES = N_DIM / BN;   // 16

// Quantized f16-integer operand copies (scratch; no allocation allowed).
static __device__ __align__(128) __half g_A16[(size_t)M_DIM * K_DIM];
static __device__ __align__(128) __half g_B16[(size_t)N_DIM * K_DIM];

// ----------------------------------------------------------------------------
// PTX helpers
// ----------------------------------------------------------------------------
__device__ __forceinline__ uint32_t smem_u32(const void* p) {
    uint32_t a;
    asm("{ .reg .u64 t; cvta.to.shared.u64 t, %1; cvt.u32.u64 %0, t; }"
        : "=r"(a) : "l"(p));
    return a;
}

#define CP_ASYNC16(dst, src) \
    asm volatile("cp.async.cg.shared.global [%0], [%1], 16;" \
                 :: "r"(dst), "l"(src) : "memory")
#define CP_COMMIT() asm volatile("cp.async.commit_group;" ::: "memory")
#define CP_WAIT1()  asm volatile("cp.async.wait_group 1;"  ::: "memory")

#define LDSM4(r, addr) \
    asm volatile("ldmatrix.sync.aligned.m8n8.x4.shared.b16 {%0,%1,%2,%3}, [%4];" \
                 : "=r"((r)[0]), "=r"((r)[1]), "=r"((r)[2]), "=r"((r)[3]) \
                 : "r"(addr))

#define MMA16816(d, a, b0, b1) \
    asm volatile("mma.sync.aligned.m16n8k16.row.col.f32.f16.f16.f32 " \
                 "{%0,%1,%2,%3}, {%4,%5,%6,%7}, {%8,%9}, {%0,%1,%2,%3};" \
                 : "+f"((d)[0]), "+f"((d)[1]), "+f"((d)[2]), "+f"((d)[3]) \
                 : "r"((a)[0]), "r"((a)[1]), "r"((a)[2]), "r"((a)[3]), \
                   "r"(b0), "r"(b1))

// ----------------------------------------------------------------------------
// Quantize-to-f16 pack kernel (74% DRAM roofline; unchanged)
// ----------------------------------------------------------------------------
__global__ void __launch_bounds__(256) quant_kernel(const float* __restrict__ s,
                                                    __half* __restrict__ d) {
    const size_t i = ((size_t)blockIdx.x * 256 + threadIdx.x) * 8;
    const float4 v0 = *reinterpret_cast<const float4*>(s + i);
    const float4 v1 = *reinterpret_cast<const float4*>(s + i + 4);
    unsigned short h[8];
    h[0] = __half_as_ushort(__float2half_rn(rintf(__fdiv_rn(v0.x, U_F))));
    h[1] = __half_as_ushort(__float2half_rn(rintf(__fdiv_rn(v0.y, U_F))));
    h[2] = __half_as_ushort(__float2half_rn(rintf(__fdiv_rn(v0.z, U_F))));
    h[3] = __half_as_ushort(__float2half_rn(rintf(__fdiv_rn(v0.w, U_F))));
    h[4] = __half_as_ushort(__float2half_rn(rintf(__fdiv_rn(v1.x, U_F))));
    h[5] = __half_as_ushort(__float2half_rn(rintf(__fdiv_rn(v1.y, U_F))));
    h[6] = __half_as_ushort(__float2half_rn(rintf(__fdiv_rn(v1.z, U_F))));
    h[7] = __half_as_ushort(__float2half_rn(rintf(__fdiv_rn(v1.w, U_F))));
    uint4 p;
    p.x = (uint32_t)h[0] | ((uint32_t)h[1] << 16);
    p.y = (uint32_t)h[2] | ((uint32_t)h[3] << 16);
    p.z = (uint32_t)h[4] | ((uint32_t)h[5] << 16);
    p.w = (uint32_t)h[6] | ((uint32_t)h[7] << 16);
    *reinterpret_cast<uint4*>(d + i) = p;
}

// ----------------------------------------------------------------------------
// Stage loader: A 16KB (1024 x 16B), B 32KB (2048 x 16B), XOR-swizzled rows.
// ----------------------------------------------------------------------------
__device__ __forceinline__ void load_stage(uint32_t sbase, int mbase, int nbase,
                                           int kbase, int tid) {
#pragma unroll
    for (int i = 0; i < 4; i++) {
        const int c = tid + i * 256;
        const int row = c >> 3, col16 = c & 7;
        const uint32_t dst = sbase + row * 128 + ((col16 ^ (row & 7)) << 4);
        const void* src = g_A16 + (size_t)(mbase + row) * K_DIM + kbase + col16 * 8;
        CP_ASYNC16(dst, src);
    }
#pragma unroll
    for (int i = 0; i < 8; i++) {
        const int c = tid + i * 256;
        const int row = c >> 3, col16 = c & 7;
        const uint32_t dst = sbase + A_STAGE_BYTES + row * 128 + ((col16 ^ (row & 7)) << 4);
        const void* src = g_B16 + (size_t)(nbase + row) * K_DIM + kbase + col16 * 8;
        CP_ASYNC16(dst, src);
    }
}

// ----------------------------------------------------------------------------
// GEMM: 128x256x64 CTA tile, 3-stage cp.async pipeline, 8 warps (2M x 4N),
// warp tile 64x64 via mma.sync m16n8k16, fused pi-quantize epilogue.
// ----------------------------------------------------------------------------
__global__ void __launch_bounds__(256, 1)
gemm_kernel(const float* __restrict__ bias, float* __restrict__ out) {
    extern __shared__ __align__(1024) char smem[];
    const uint32_t sbase = smem_u32(smem);
    const int tid = threadIdx.x;
    const int lane = tid & 31;
    const int w = tid >> 5;

    // banded rasterization: 8 m-tiles x 16 n-tiles per band (128 CTAs/band)
    const int bid = blockIdx.x;
    const int band = bid >> 7;
    const int rem = bid & 127;
    const int mt = band * 8 + (rem & 7);
    const int nt = rem >> 3;
    const int mbase = mt * BM, nbase = nt * BN;

    // prologue: fill STAGES-1 = 2 stages (k-tiles 0 and 1)
#pragma unroll
    for (int s = 0; s < STAGES - 1; s++) {
        load_stage(sbase + s * STAGE_BYTES, mbase, nbase, s * BK, tid);
        CP_COMMIT();
    }

    const int mwarp = w >> 2;        // 0..1 -> 64-row slices
    const int nwarp = w & 3;         // 0..3 -> 64-col slices
    const int x7 = lane & 7;

    // per-lane invariant smem byte offsets (relative to stage base)
    uint32_t aoff[4], boff[4];
#pragma unroll
    for (int mi = 0; mi < 4; mi++)
        aoff[mi] = (uint32_t)((mwarp * 64 + mi * 16 + (lane & 15)) << 7);
#pragma unroll
    for (int nb = 0; nb < 4; nb++)
        boff[nb] = (uint32_t)(A_STAGE_BYTES +
                   ((nwarp * 64 + nb * 16 + (lane & 7) + ((lane >> 4) << 3)) << 7));
    const int acol = lane >> 4;          // A: +8 in k for lanes 16-31
    const int bcol = (lane >> 3) & 1;    // B: +8 in k pattern

    float acc[4][8][4];
#pragma unroll
    for (int mi = 0; mi < 4; mi++)
#pragma unroll
        for (int nj = 0; nj < 8; nj++)
#pragma unroll
            for (int e = 0; e < 4; e++) acc[mi][nj][e] = 0.f;

    // rolling stage cursors
    int cmp_s = 0;
    int ld_s  = STAGES - 1;

    for (int kt = 0; kt < KT; kt++) {
        CP_WAIT1();
        __syncthreads();
        const int next = kt + STAGES - 1;
        if (next < KT) {
            load_stage(sbase + ld_s * STAGE_BYTES, mbase, nbase, next * BK, tid);
        }
        CP_COMMIT();
        ld_s = (ld_s + 1 == STAGES) ? 0 : ld_s + 1;

        const uint32_t st = sbase + cmp_s * STAGE_BYTES;
        cmp_s = (cmp_s + 1 == STAGES) ? 0 : cmp_s + 1;
#pragma unroll
        for (int ks = 0; ks < 4; ks++) {
            uint32_t a[4][4], b[4][4];
#pragma unroll
            for (int nb = 0; nb < 4; nb++)
                LDSM4(b[nb], st + boff[nb] + ((uint32_t)((ks * 2 + bcol) ^ x7) << 4));
#pragma unroll
            for (int mi = 0; mi < 4; mi++)
                LDSM4(a[mi], st + aoff[mi] + ((uint32_t)((ks * 2 + acol) ^ x7) << 4));
#pragma unroll
            for (int mi = 0; mi < 4; mi++)
#pragma unroll
                for (int nj = 0; nj < 8; nj++)
                    MMA16816(acc[mi][nj], a[mi],
                             b[nj >> 1][(nj & 1) * 2], b[nj >> 1][(nj & 1) * 2 + 1]);
        }
    }

    // ---- epilogue: exact S -> qz(S*u) (+bias) -> qz -> GMEM ----
    const int row0 = mbase + mwarp * 64;
    const int col0 = nbase + nwarp * 64;
    const int tr = lane >> 2;
    const int tc = (lane & 3) * 2;
#pragma unroll
    for (int mi = 0; mi < 4; mi++) {
#pragma unroll
        for (int rr = 0; rr < 2; rr++) {
            const int row = row0 + mi * 16 + rr * 8 + tr;
            float* orow = out + (size_t)row * N_DIM + col0;
#pragma unroll
            for (int nj = 0; nj < 8; nj++) {
                const int c = nj * 8 + tc;
                float2 o;
#pragma unroll
                for (int e = 0; e < 2; e++) {
                    const float sv = acc[mi][nj][rr * 2 + e];        // exact int S
                    const float q  = rintf(__fmul_rn(sv, U_F));      // round(S*u)
                    const float cv = __fmul_rn(q, U_F);              // qz(dot)
                    const float tv = cv + __ldg(bias + col0 + c + e);// + bias
                    (&o.x)[e] = __fmul_rn(rintf(__fmul_rn(tv, INVU_F)), U_F);
                }
                *reinterpret_cast<float2*>(orow + c) = o;
            }
        }
    }
}

// ----------------------------------------------------------------------------
// Host launcher (graph-capturable: kernel launches only)
// ----------------------------------------------------------------------------
extern "C" void kernel_launch(void* const* d_in, const int* in_sizes, int n_in,
                              void* d_out, int out_size) {
    const float* x = (const float*)d_in[0];   // [8192, 4096]
    const float* wgt = (const float*)d_in[1]; // [4096, 4096]
    const float* b = (const float*)d_in[2];   // [4096]
    float* out = (float*)d_out;               // [8192, 4096]

    void* a16 = nullptr; void* b16 = nullptr;
    cudaGetSymbolAddress(&a16, g_A16);
    cudaGetSymbolAddress(&b16, g_B16);

    quant_kernel<<<(int)(((size_t)M_DIM * K_DIM / 8) / 256), 256>>>(x, (__half*)a16);
    quant_kernel<<<(int)(((size_t)N_DIM * K_DIM / 8) / 256), 256>>>(wgt, (__half*)b16);

    static bool attr_set = false;
    if (!attr_set) {
        cudaFuncSetAttribute(gemm_kernel,
                             cudaFuncAttributeMaxDynamicSharedMemorySize, SMEM_SIZE);
        attr_set = true;
    }
    gemm_kernel<<<MTILES * NTILES, 256, SMEM_SIZE>>>(b, out);
}